// round 3
// baseline (speedup 1.0000x reference)
#include <cuda_runtime.h>

#define NB 32
#define NN 400
#define NC 720
#define NH 12
#define HD 60
#define SCALE 0.1290994448735806f   // 60^-0.5

// Scratch: q/k projected, (b,h,n,e) layout; roi validity per (b,n)
__device__ float g_q[NB * NH * NN * HD];
__device__ float g_k[NB * NH * NN * HD];
__device__ int   g_roi[NB * NN];

// ---------------------------------------------------------------------------
// Kernel 1: roi_mask[b][n] = any_c mask[b][c][n] != 0   (mask is (B, C, N))
// ---------------------------------------------------------------------------
__global__ __launch_bounds__(128) void roi_kernel(const int* __restrict__ mask) {
    int b = blockIdx.y;
    int n = blockIdx.x * blockDim.x + threadIdx.x;
    if (n >= NN) return;
    const int* p = mask + (size_t)b * NC * NN + n;
    int s = 0;
    for (int c = 0; c < NC; ++c) s |= p[(size_t)c * NN];
    g_roi[b * NN + n] = s;
}

// ---------------------------------------------------------------------------
// Kernel 2: Q/K projection. out[i][j] = sum_c x[i][c] * w[j][c], j in [0,1440)
// i = b*400+n.  j<720 -> q (scaled), j>=720 -> k.  Scatter to (b,h,n,e).
// 64x64 tile, BK=16, 256 threads, 4x4 per thread.
// ---------------------------------------------------------------------------
__global__ __launch_bounds__(256) void qk_proj(const float* __restrict__ x,
                                               const float* __restrict__ w) {
    __shared__ float As[16][64];
    __shared__ float Ws[16][64];
    int tid = threadIdx.x;
    int row0 = blockIdx.y * 64;
    int col0 = blockIdx.x * 64;
    int lr = tid >> 2;
    int lk = (tid & 3) << 2;
    int ty = tid >> 4, tx = tid & 15;
    float acc[4][4] = {};

    for (int kk = 0; kk < NC; kk += 16) {
        float4 av = *(const float4*)(x + (size_t)(row0 + lr) * NC + kk + lk);
        float4 wv = make_float4(0.f, 0.f, 0.f, 0.f);
        int jr = col0 + lr;
        if (jr < 2 * NC) wv = *(const float4*)(w + (size_t)jr * NC + kk + lk);
        As[lk + 0][lr] = av.x; As[lk + 1][lr] = av.y;
        As[lk + 2][lr] = av.z; As[lk + 3][lr] = av.w;
        Ws[lk + 0][lr] = wv.x; Ws[lk + 1][lr] = wv.y;
        Ws[lk + 2][lr] = wv.z; Ws[lk + 3][lr] = wv.w;
        __syncthreads();
#pragma unroll
        for (int k = 0; k < 16; ++k) {
            float4 a = *(const float4*)&As[k][ty * 4];
            float4 b = *(const float4*)&Ws[k][tx * 4];
            float aa[4] = {a.x, a.y, a.z, a.w};
            float bb[4] = {b.x, b.y, b.z, b.w};
#pragma unroll
            for (int i = 0; i < 4; ++i)
#pragma unroll
                for (int j = 0; j < 4; ++j) acc[i][j] += aa[i] * bb[j];
        }
        __syncthreads();
    }

#pragma unroll
    for (int i = 0; i < 4; ++i) {
        int gi = row0 + ty * 4 + i;           // global x-row
        int b = gi / NN, n = gi - b * NN;
#pragma unroll
        for (int j = 0; j < 4; ++j) {
            int jc = col0 + tx * 4 + j;
            if (jc < 2 * NC) {
                int t = jc / NC;
                int r = jc - t * NC;
                int h = r / HD, e = r - h * HD;
                size_t off = ((size_t)(b * NH + h) * NN + n) * HD + e;
                float v = acc[i][j];
                if (t == 0) g_q[off] = v * SCALE;
                else        g_k[off] = v;
            }
        }
    }
}

// ---------------------------------------------------------------------------
// Kernel 3: masked logits -> d_out.  Per block: one (b,h), 64x64 (n,m) tile.
// logit[n][m] = dot(q[n,:], k[m,:])  (q pre-scaled), or -10000 if roi[m]==0.
// ---------------------------------------------------------------------------
__global__ __launch_bounds__(256) void logits_kernel(float* __restrict__ out) {
    __shared__ float qs[HD][64];
    __shared__ float ks[HD][64];
    int bh = blockIdx.z;
    int n0 = blockIdx.y * 64;
    int m0 = blockIdx.x * 64;
    const float* qb = g_q + (size_t)bh * NN * HD;
    const float* kb = g_k + (size_t)bh * NN * HD;
    int tid = threadIdx.x;

    for (int idx = tid; idx < 64 * HD; idx += 256) {
        int r = idx / HD, e = idx - r * HD;
        int n = n0 + r;
        qs[e][r] = (n < NN) ? qb[(size_t)n * HD + e] : 0.f;
        int m = m0 + r;
        ks[e][r] = (m < NN) ? kb[(size_t)m * HD + e] : 0.f;
    }
    __syncthreads();

    int ty = tid >> 4, tx = tid & 15;
    float acc[4][4] = {};
#pragma unroll
    for (int e = 0; e < HD; ++e) {
        float4 a = *(const float4*)&qs[e][ty * 4];
        float4 b = *(const float4*)&ks[e][tx * 4];
        float aa[4] = {a.x, a.y, a.z, a.w};
        float bb[4] = {b.x, b.y, b.z, b.w};
#pragma unroll
        for (int i = 0; i < 4; ++i)
#pragma unroll
            for (int j = 0; j < 4; ++j) acc[i][j] += aa[i] * bb[j];
    }

    int b = bh / NH;
    const int* roi = g_roi + b * NN;
    float* ob = out + (size_t)bh * NN * NN;
#pragma unroll
    for (int i = 0; i < 4; ++i) {
        int n = n0 + ty * 4 + i;
        if (n < NN) {
#pragma unroll
            for (int j = 0; j < 4; ++j) {
                int m = m0 + tx * 4 + j;
                if (m < NN)
                    ob[(size_t)n * NN + m] = roi[m] ? acc[i][j] : -10000.0f;
            }
        }
    }
}

// ---------------------------------------------------------------------------
// Kernel 4: in-place softmax over last dim (400) of d_out. 1 block per row.
// ---------------------------------------------------------------------------
__global__ __launch_bounds__(128) void softmax_kernel(float* __restrict__ out) {
    size_t row = blockIdx.x;
    float* p = out + row * (size_t)NN;
    int t = threadIdx.x;
    __shared__ float rm[4], rs[4];

    float v[4];
    float mx = -3.0e38f;
#pragma unroll
    for (int i = 0; i < 4; ++i) {
        int idx = t + i * 128;
        v[i] = (idx < NN) ? p[idx] : -3.0e38f;
        mx = fmaxf(mx, v[i]);
    }
#pragma unroll
    for (int o = 16; o; o >>= 1) mx = fmaxf(mx, __shfl_xor_sync(0xffffffffu, mx, o));
    if ((t & 31) == 0) rm[t >> 5] = mx;
    __syncthreads();
    mx = fmaxf(fmaxf(rm[0], rm[1]), fmaxf(rm[2], rm[3]));

    float s = 0.f;
#pragma unroll
    for (int i = 0; i < 4; ++i) {
        float e = __expf(v[i] - mx);
        v[i] = e;
        int idx = t + i * 128;
        if (idx < NN) s += e;
    }
#pragma unroll
    for (int o = 16; o; o >>= 1) s += __shfl_xor_sync(0xffffffffu, s, o);
    if ((t & 31) == 0) rs[t >> 5] = s;
    __syncthreads();
    s = rs[0] + rs[1] + rs[2] + rs[3];
    float inv = 1.0f / s;
#pragma unroll
    for (int i = 0; i < 4; ++i) {
        int idx = t + i * 128;
        if (idx < NN) p[idx] = v[i] * inv;
    }
}

// ---------------------------------------------------------------------------
extern "C" void kernel_launch(void* const* d_in, const int* in_sizes, int n_in,
                              void* d_out, int out_size) {
    const float* x    = (const float*)d_in[0];   // (32, 400, 720) fp32
    const int*   mask = (const int*)d_in[1];     // (32, 720, 400) int32
    const float* w    = (const float*)d_in[2];   // (2160, 720) fp32
    float* out = (float*)d_out;                  // (32, 12, 400, 400) fp32

    roi_kernel<<<dim3((NN + 127) / 128, NB), 128>>>(mask);
    qk_proj<<<dim3((2 * NC + 63) / 64, (NB * NN) / 64), 256>>>(x, w);
    logits_kernel<<<dim3((NN + 63) / 64, (NN + 63) / 64, NB * NH), 256>>>(out);
    softmax_kernel<<<NB * NH * NN, 128>>>(out);
}